// round 2
// baseline (speedup 1.0000x reference)
#include <cuda_runtime.h>

// Problem constants
#define W_DIM 512
#define H_DIM 512
#define B_DIM 8
#define C_DIM 32
#define NBLK  128           // 8 batches * 16 row-tiles of 32 rows
#define NTHR  256

// Scratch: transposed input/output in (W, B, H, C) layout, C contiguous.
__device__ float    g_Xt[W_DIM * B_DIM * H_DIM * C_DIM];   // 256 MB
__device__ float    g_Yt[W_DIM * B_DIM * H_DIM * C_DIM];   // 256 MB
__device__ unsigned g_progress[NBLK];                       // monotonic counters

using u64 = unsigned long long;

// ---- f32x2 packed helpers (sm_103a) ---------------------------------------
__device__ __forceinline__ void fma2(u64& acc, u64 a, u64 b) {
    asm("fma.rn.f32x2 %0, %1, %2, %0;" : "+l"(acc) : "l"(a), "l"(b));
}
__device__ __forceinline__ u64 pack2(float lo, float hi) {
    u64 r; asm("mov.b64 %0, {%1, %2};" : "=l"(r) : "f"(lo), "f"(hi)); return r;
}
__device__ __forceinline__ float hadd2(u64 v) {
    float lo, hi; asm("mov.b64 {%0, %1}, %2;" : "=f"(lo), "=f"(hi) : "l"(v));
    return lo + hi;
}
__device__ __forceinline__ float tanh_fast(float x) {
    float y; asm("tanh.approx.f32 %0, %1;" : "=f"(y) : "f"(x)); return y;
}
__device__ __forceinline__ float sigmoid_fast(float x) {
    return __fdividef(1.0f, 1.0f + __expf(-x));
}

// ---- acquire/release flag ops ---------------------------------------------
__device__ __forceinline__ unsigned ld_acq(const unsigned* p) {
    unsigned v; asm volatile("ld.acquire.gpu.global.u32 %0, [%1];" : "=r"(v) : "l"(p)); return v;
}
__device__ __forceinline__ void st_rel(unsigned* p, unsigned v) {
    asm volatile("st.release.gpu.global.u32 [%0], %1;" :: "l"(p), "r"(v));
}

// ---------------------------------------------------------------------------
// Transpose (B,C,H,W) -> (W,B,H,C)
// ---------------------------------------------------------------------------
__global__ __launch_bounds__(256) void transpose_in_kernel(const float* __restrict__ states) {
    __shared__ float tile[32][33];
    const int wt = blockIdx.x, h = blockIdx.y, b = blockIdx.z;
    const int w0 = wt * 32;
    const int t  = threadIdx.x;
    const int lo = t & 31, g = t >> 5;
#pragma unroll
    for (int i = 0; i < 4; ++i) {
        int cc = g * 4 + i;
        tile[cc][lo] = states[((size_t)(b * 32 + cc) * 512 + h) * 512 + (w0 + lo)];
    }
    __syncthreads();
#pragma unroll
    for (int i = 0; i < 4; ++i) {
        int ww = g * 4 + i;
        g_Xt[((size_t)((w0 + ww) * 8 + b) * 512 + h) * 32 + lo] = tile[lo][ww];
    }
}

// ---------------------------------------------------------------------------
// Transpose (W,B,H,C) -> (B,C,H,W)
// ---------------------------------------------------------------------------
__global__ __launch_bounds__(256) void transpose_out_kernel(float* __restrict__ out) {
    __shared__ float tile[32][33];
    const int wt = blockIdx.x, h = blockIdx.y, b = blockIdx.z;
    const int w0 = wt * 32;
    const int t  = threadIdx.x;
    const int lo = t & 31, g = t >> 5;
#pragma unroll
    for (int i = 0; i < 4; ++i) {
        int ww = g * 4 + i;
        tile[ww][lo] = g_Yt[((size_t)((w0 + ww) * 8 + b) * 512 + h) * 32 + lo];
    }
    __syncthreads();
#pragma unroll
    for (int i = 0; i < 4; ++i) {
        int cc = g * 4 + i;
        out[((size_t)(b * 32 + cc) * 512 + h) * 512 + (w0 + lo)] = tile[lo][cc];
    }
}

// ---------------------------------------------------------------------------
// Persistent scan kernel. 128 blocks, each owns 32 (b,h) rows for all 511
// steps. Previous output column lives in double-buffered smem tiles; halo
// rows come from neighbor blocks via g_Yt + acquire/release progress flags.
//
// smem layout (floats):
//   sWih : 96 x 100 (stride % 32 == 4 -> conflict-free float4)  = 9600
//   sWhh : 96 x 36                                              = 3456
//   buf0 : 34 x 32  (column, + 2 halo rows)                     = 1088
//   buf1 : 34 x 32                                              = 1088
//   sCur : 32 x 32  (current input column)                      = 1024
// total 16256 floats = 65024 bytes (dynamic)
// ---------------------------------------------------------------------------
#define SM_WIH 0
#define SM_WHH (SM_WIH + 96 * 100)
#define SM_BUF0 (SM_WHH + 96 * 36)
#define SM_BUF1 (SM_BUF0 + 34 * 32)
#define SM_CUR  (SM_BUF1 + 34 * 32)
#define SM_FLOATS (SM_CUR + 32 * 32)

__global__ __launch_bounds__(NTHR, 1) void scan_kernel(
    const float* __restrict__ Wih, const float* __restrict__ bih,
    const float* __restrict__ Whh, const float* __restrict__ bhh)
{
    extern __shared__ float sm[];
    float* sWih = sm + SM_WIH;
    float* sWhh = sm + SM_WHH;
    float* buf0 = sm + SM_BUF0;
    float* buf1 = sm + SM_BUF1;
    float* sCur = sm + SM_CUR;
    __shared__ unsigned sBase;

    const int tid  = threadIdx.x;
    const int beta = blockIdx.x;
    const int b    = beta >> 4;
    const int tile = beta & 15;
    const int h0   = tile * 32;
    const int c    = tid & 31;        // channel
    const int rq   = tid >> 5;        // row quad (0..7): rows rq*4 .. rq*4+3

    if (tid == 0) sBase = ld_acq(&g_progress[beta]);

    for (int i = tid; i < 96 * 96; i += NTHR) sWih[(i / 96) * 100 + (i % 96)] = Wih[i];
    for (int i = tid; i < 96 * 32; i += NTHR) sWhh[(i / 32) * 36  + (i % 32)] = Whh[i];

    const float br0 = bih[c]      + bhh[c];
    const float bz0 = bih[32 + c] + bhh[32 + c];
    const float bni = bih[64 + c];
    const float bnh = bhh[64 + c];
    const u64 br2 = pack2(br0, 0.0f);
    const u64 bz2 = pack2(bz0, 0.0f);
    const u64 bni2 = pack2(bni, 0.0f);
    const u64 bnh2 = pack2(bnh, 0.0f);

    // zero halo slots of both buffers (edge tiles never overwrite them)
    if (tid < 32) { buf0[tid] = 0.0f; buf1[tid] = 0.0f; }
    else if (tid < 64) { buf0[33 * 32 + (tid - 32)] = 0.0f; buf1[33 * 32 + (tid - 32)] = 0.0f; }
    __syncthreads();

    // Publish column 0 = input column 0 (identity passthrough) into buf0
    for (int i = tid; i < 1024; i += NTHR) {
        int r = i >> 5, cc = i & 31;
        size_t gi = ((size_t)b * 512 + (h0 + r)) * 32 + cc;   // w = 0
        float v = g_Xt[gi];
        buf0[(1 + r) * 32 + cc] = v;
        __stcg(&g_Yt[gi], v);
    }
    __syncthreads();
    if (tid == 0) st_rel(&g_progress[beta], sBase + 1);

    for (int w = 1; w < W_DIM; ++w) {
        float* bufPrev = ((w - 1) & 1) ? buf1 : buf0;   // holds column w-1
        float* bufCur  = (w & 1)       ? buf1 : buf0;   // receives column w

        // Current input column, coalesced float4 (256 threads x 16B = 4 KB)
        {
            const float4* src = (const float4*)&g_Xt[((size_t)(w * 8 + b) * 512 + h0) * 32];
            ((float4*)sCur)[tid] = src[tid];
        }

        // Warps 0/1: wait for +-1 neighbor to publish column w-1, fetch halos
        if (tid < 64) {
            const bool down = tid < 32;
            const int  lane = tid & 31;
            const bool valid = down ? (tile > 0) : (tile < 15);
            if (valid) {
                const int nb = down ? beta - 1 : beta + 1;
                if (lane == 0) {
                    const unsigned tgt = sBase + (unsigned)w;
                    while (ld_acq(&g_progress[nb]) < tgt) { }
                }
                __syncwarp();
                const int hh = down ? (h0 - 1) : (h0 + 32);
                float v = __ldcg(&g_Yt[((size_t)((w - 1) * 8 + b) * 512 + hh) * 32 + lane]);
                bufPrev[(down ? 0 : 33) * 32 + lane] = v;
            }
        }
        __syncthreads();

        // ---- compute: 4 rows x 1 channel per thread, packed f32x2 ---------
        u64 ar2[4], az2[4], ani2[4], anh2[4];
#pragma unroll
        for (int i = 0; i < 4; ++i) { ar2[i] = br2; az2[i] = bz2; ani2[i] = bni2; anh2[i] = bnh2; }

        // i-part: x(96 = prev rows h-1,h,h+1 contiguous in bufPrev) @ Wih^T
#pragma unroll 8
        for (int kq = 0; kq < 24; ++kq) {
            ulonglong2 wr = *(const ulonglong2*)&sWih[(c)      * 100 + kq * 4];
            ulonglong2 wz = *(const ulonglong2*)&sWih[(32 + c) * 100 + kq * 4];
            ulonglong2 wn = *(const ulonglong2*)&sWih[(64 + c) * 100 + kq * 4];
#pragma unroll
            for (int i = 0; i < 4; ++i) {
                ulonglong2 xv = *(const ulonglong2*)&bufPrev[(rq * 4 + i) * 32 + kq * 4];
                fma2(ar2[i],  xv.x, wr.x);  fma2(ar2[i],  xv.y, wr.y);
                fma2(az2[i],  xv.x, wz.x);  fma2(az2[i],  xv.y, wz.y);
                fma2(ani2[i], xv.x, wn.x);  fma2(ani2[i], xv.y, wn.y);
            }
        }
        // h-part: cur col (32) @ Whh^T
#pragma unroll
        for (int kq = 0; kq < 8; ++kq) {
            ulonglong2 wr = *(const ulonglong2*)&sWhh[(c)      * 36 + kq * 4];
            ulonglong2 wz = *(const ulonglong2*)&sWhh[(32 + c) * 36 + kq * 4];
            ulonglong2 wn = *(const ulonglong2*)&sWhh[(64 + c) * 36 + kq * 4];
#pragma unroll
            for (int i = 0; i < 4; ++i) {
                ulonglong2 hv = *(const ulonglong2*)&sCur[(rq * 4 + i) * 32 + kq * 4];
                fma2(ar2[i],  hv.x, wr.x);  fma2(ar2[i],  hv.y, wr.y);
                fma2(az2[i],  hv.x, wz.x);  fma2(az2[i],  hv.y, wz.y);
                fma2(anh2[i], hv.x, wn.x);  fma2(anh2[i], hv.y, wn.y);
            }
        }

        float outv[4];
#pragma unroll
        for (int i = 0; i < 4; ++i) {
            float ar_  = hadd2(ar2[i]);
            float az_  = hadd2(az2[i]);
            float ani_ = hadd2(ani2[i]);
            float anh_ = hadd2(anh2[i]);
            float rg = sigmoid_fast(ar_);
            float zg = sigmoid_fast(az_);
            float ng = tanh_fast(fmaf(rg, anh_, ani_));
            float cv = sCur[(rq * 4 + i) * 32 + c];
            outv[i]  = fmaf(ng - cv, zg, cv);   // n*z + cur*(1-z)
        }

        // write own rows into the other buffer (no read hazard) + global
#pragma unroll
        for (int i = 0; i < 4; ++i) {
            int r = rq * 4 + i;
            bufCur[(1 + r) * 32 + c] = outv[i];
            __stcg(&g_Yt[((size_t)(w * 8 + b) * 512 + (h0 + r)) * 32 + c], outv[i]);
        }
        __syncthreads();
        if (tid == 0) st_rel(&g_progress[beta], sBase + (unsigned)(w + 1));
    }
}

// ---------------------------------------------------------------------------
extern "C" void kernel_launch(void* const* d_in, const int* in_sizes, int n_in,
                              void* d_out, int out_size) {
    const float* states = (const float*)d_in[0];
    const float* wih    = (const float*)d_in[1];
    const float* bih    = (const float*)d_in[2];
    const float* whh    = (const float*)d_in[3];
    const float* bhh    = (const float*)d_in[4];
    float* out = (float*)d_out;

    cudaFuncSetAttribute(scan_kernel, cudaFuncAttributeMaxDynamicSharedMemorySize,
                         SM_FLOATS * (int)sizeof(float));

    dim3 tgrid(W_DIM / 32, H_DIM, B_DIM);
    transpose_in_kernel<<<tgrid, 256>>>(states);
    scan_kernel<<<NBLK, NTHR, SM_FLOATS * sizeof(float)>>>(wih, bih, whh, bhh);
    transpose_out_kernel<<<tgrid, 256>>>(out);
}